// round 2
// baseline (speedup 1.0000x reference)
#include <cuda_runtime.h>

#define K_CODES 16384
#define NSAMP   4096
#define DIM     14
#define HW      1024
#define Q_ELEMS 57344            // 4 * 14 * 1024

// Module-load zero-initialized. g_avg is cycled back to zero by lfq_avg_partial
// every call, so each execution (eager correctness run or graph replay) sees
// zeros. g_ent/g_partial are fully overwritten every call.
__device__ float g_avg[K_CODES];
__device__ float g_ent[NSAMP];
__device__ float g_partial[16];

// ---------------------------------------------------------------------------
// Kernel A: one thread per sample.
//   - load 14 channel values (coalesced: lane -> consecutive n)
//   - write q = sign(x) (coalesced), emit big-endian index
//   - analytic softmax max (= code sign(xn)); enumerate only codes within
//     dz > -30 of it: subsets of dims with flip-cost 400*|xn_j| < 30.
//     Dropped terms are < e^-30 relative — below fp32 noise in the reference.
// ---------------------------------------------------------------------------
__global__ __launch_bounds__(128) void lfq_sample(const float* __restrict__ x,
                                                  float* __restrict__ out) {
    const int s = blockIdx.x * blockDim.x + threadIdx.x;
    if (s >= NSAMP) return;
    const int b = s >> 10;
    const int n = s & (HW - 1);

    const float* xs = x   + (b * DIM) * HW + n;
    float*       qo = out + (b * DIM) * HW + n;

    float v[DIM];
    float ss = 0.0f;
#pragma unroll
    for (int j = 0; j < DIM; j++) {
        v[j] = xs[j * HW];
        ss += v[j] * v[j];
    }
    const float inv = rsqrtf(ss);

    int idx = 0;
#pragma unroll
    for (int j = 0; j < DIM; j++) {
        const bool pos = v[j] > 0.0f;
        qo[j * HW] = pos ? 1.0f : -1.0f;
        if (pos) idx |= (1 << (13 - j));
    }
    out[Q_ELEMS + 1 + s] = (float)idx;

    // Flip costs: a_j = 400 * |xn_j| = -delta(z) for flipping dim j.
    // Collect the dims that can possibly appear in a survivor (a_j < 30).
    float small_c[DIM];
    int   small_t[DIM];
    int m = 0;
#pragma unroll
    for (int j = 0; j < DIM; j++) {
        const float a = 400.0f * fabsf(v[j]) * inv;
        if (a < 30.0f) {
            small_c[m] = a;
            small_t[m] = 1 << (13 - j);
            m++;
        }
    }

    // Pass 1 over subsets: S = sum exp(dz), T = sum dz*exp(dz), dz = -cost.
    const int nm = 1 << m;
    float S = 0.0f, T = 0.0f;
    for (int mask = 0; mask < nm; mask++) {
        float c = 0.0f;
        int mm = mask;
        while (mm) {
            const int p = __ffs(mm) - 1;
            c += small_c[p];
            mm &= mm - 1;
        }
        if (c < 30.0f) {
            const float e = __expf(-c);
            S += e;
            T -= c * e;
        }
    }

    // entropy = logS - T/S  (max cancels)
    g_ent[s] = logf(S) - T / S;

    // Pass 2: scatter probs of survivors into the codebook histogram.
    const float invS = 1.0f / S;
    for (int mask = 0; mask < nm; mask++) {
        float c = 0.0f;
        int tog = 0;
        int mm = mask;
        while (mm) {
            const int p = __ffs(mm) - 1;
            c += small_c[p];
            tog ^= small_t[p];
            mm &= mm - 1;
        }
        if (c < 30.0f)
            atomicAdd(&g_avg[idx ^ tog], __expf(-c) * invS);
    }
}

// ---------------------------------------------------------------------------
// Kernel B: 16 blocks x 256 threads. Partial sum of avg*log(avg+eps) over the
// 16384-code histogram; zero the histogram behind us for the next replay.
// ---------------------------------------------------------------------------
__global__ __launch_bounds__(256) void lfq_avg_partial() {
    __shared__ float red[256];
    const int tid  = threadIdx.x;
    const int base = blockIdx.x * 1024;
    const float scale = 1.0f / (float)NSAMP;

    float ms = 0.0f;
#pragma unroll
    for (int t = 0; t < 4; t++) {
        const int i = base + t * 256 + tid;
        const float a = g_avg[i] * scale;
        ms += a * logf(a + 1e-9f);
        g_avg[i] = 0.0f;
    }
    red[tid] = ms;
    __syncthreads();
    for (int off = 128; off > 0; off >>= 1) {
        if (tid < off) red[tid] += red[tid + off];
        __syncthreads();
    }
    if (tid == 0) g_partial[blockIdx.x] = red[0];
}

// ---------------------------------------------------------------------------
// Kernel C: combine entropy mean + histogram partials -> el scalar.
// ---------------------------------------------------------------------------
__global__ __launch_bounds__(256) void lfq_finalize(float* __restrict__ out) {
    __shared__ float red[256];
    const int tid = threadIdx.x;

    float es = 0.0f;
#pragma unroll
    for (int i = 0; i < NSAMP / 256; i++) es += g_ent[i * 256 + tid];

    float ms = (tid < 16) ? g_partial[tid] : 0.0f;

    red[tid] = es;
    __syncthreads();
    for (int off = 128; off > 0; off >>= 1) {
        if (tid < off) red[tid] += red[tid + off];
        __syncthreads();
    }
    const float ent_sum = red[0];
    __syncthreads();
    red[tid] = ms;
    __syncthreads();
    for (int off = 128; off > 0; off >>= 1) {
        if (tid < off) red[tid] += red[tid + off];
        __syncthreads();
    }
    if (tid == 0) {
        // el = entro_mean - mean_entro = ent_sum/NSAMP + sum a*log(a+eps)
        out[Q_ELEMS] = ent_sum * (1.0f / (float)NSAMP) + red[0];
    }
}

extern "C" void kernel_launch(void* const* d_in, const int* in_sizes, int n_in,
                              void* d_out, int out_size) {
    const float* x = (const float*)d_in[0];
    float* out = (float*)d_out;

    lfq_sample<<<NSAMP / 128, 128>>>(x, out);
    lfq_avg_partial<<<16, 256>>>();
    lfq_finalize<<<1, 256>>>(out);
}

// round 3
// speedup vs baseline: 11.4707x; 11.4707x over previous
#include <cuda_runtime.h>

#define K_CODES 16384
#define NSAMP   4096
#define DIM     14
#define HW      1024
#define Q_ELEMS 57344            // 4 * 14 * 1024
#define TPB     32               // one warp per block

// Module-load zero-initialized; each call restores zeros behind itself so
// every execution (eager run or graph replay) starts from the same state.
__device__ float g_avg[K_CODES];
__device__ float g_ent_sum;
__device__ float g_hist_sum;

// ---------------------------------------------------------------------------
// Kernel A: one warp per block, one sample per lane (phase 1), then the warp
// cooperatively enumerates each sample's softmax survivors (phase 2).
//
// Factorized softmax (codes are +-1 per dim -> product of Bernoullis):
//   a_j   = 400*|xn_j|           (logit cost of flipping dim j off the argmax)
//   S     = prod_j (1+e^-a_j)    -> logS = sum log1p(e^-a_j)      (exact)
//   H     = logS + sum_j a_j e^-a_j/(1+e^-a_j)                    (exact)
// Survivors for the avg_probs histogram: subsets of dims with cost sum < 30
// (dropped probs < e^-30 ~ 9e-14 -> effect on el ~ 3e-8, below fp32 noise).
// ---------------------------------------------------------------------------
__global__ __launch_bounds__(TPB) void lfq_main(const float* __restrict__ x,
                                                float* __restrict__ out) {
    __shared__ float sc[TPB][DIM];   // flip costs of small dims
    __shared__ int   st[TPB][DIM];   // index-bit toggles of small dims
    __shared__ int   smm[TPB];       // # small dims
    __shared__ int   sidx[TPB];      // argmax code index
    __shared__ float sinvS[TPB];     // 1/S

    const int lane = threadIdx.x;
    const int s    = blockIdx.x * TPB + lane;
    const int b    = s >> 10;
    const int n    = s & (HW - 1);

    const float* xs = x   + b * DIM * HW + n;   // coalesced across lanes
    float*       qo = out + b * DIM * HW + n;

    // ---- phase 1: per-thread closed-form work ----
    float v[DIM];
    float ss = 0.0f;
#pragma unroll
    for (int j = 0; j < DIM; j++) { v[j] = xs[j * HW]; ss += v[j] * v[j]; }
    const float inv = rsqrtf(ss);

    int idx = 0;
#pragma unroll
    for (int j = 0; j < DIM; j++) {
        const bool pos = v[j] > 0.0f;
        qo[j * HW] = pos ? 1.0f : -1.0f;
        if (pos) idx |= (1 << (13 - j));
    }
    out[Q_ELEMS + 1 + s] = (float)idx;
    sidx[lane] = idx;

    float logS = 0.0f, ent2 = 0.0f;
    int m = 0;
#pragma unroll
    for (int j = 0; j < DIM; j++) {
        const float a = 400.0f * fabsf(v[j]) * inv;
        const float e = __expf(-a);
        logS += log1pf(e);
        ent2 += a * e / (1.0f + e);
        if (a < 30.0f) { sc[lane][m] = a; st[lane][m] = 1 << (13 - j); m++; }
    }
    smm[lane]   = m;
    sinvS[lane] = __expf(-logS);

    float ent = logS + ent2;        // exact per-sample entropy
#pragma unroll
    for (int off = 16; off > 0; off >>= 1)
        ent += __shfl_xor_sync(0xffffffffu, ent, off);
    if (lane == 0) atomicAdd(&g_ent_sum, ent);
    __syncwarp();

    // ---- phase 2: warp-cooperative survivor scatter ----
    for (int l = 0; l < TPB; l++) {
        const int   mm   = smm[l];
        const int   nm   = 1 << mm;
        const int   bidx = sidx[l];
        const float iS   = sinvS[l];
        for (int mb = 0; mb < nm; mb += 32) {
            const int mask = mb + lane;
            if (mask < nm) {
                float c = 0.0f;
                int tog = 0;
                for (int j = 0; j < mm; j++)
                    if ((mask >> j) & 1) { c += sc[l][j]; tog ^= st[l][j]; }
                if (c < 30.0f)
                    atomicAdd(&g_avg[bidx ^ tog], __expf(-c) * iS);
            }
        }
    }
}

// ---------------------------------------------------------------------------
// Kernel B: 64 blocks x 256 threads, one histogram entry each.
// Accumulates sum_k avg*log(avg+eps) and zeroes the histogram behind itself.
// ---------------------------------------------------------------------------
__global__ __launch_bounds__(256) void lfq_hist() {
    __shared__ float wsum[8];
    const int tid = threadIdx.x;
    const int i   = blockIdx.x * 256 + tid;

    const float a = g_avg[i] * (1.0f / (float)NSAMP);
    g_avg[i] = 0.0f;
    float ms = a * logf(a + 1e-9f);

#pragma unroll
    for (int off = 16; off > 0; off >>= 1)
        ms += __shfl_xor_sync(0xffffffffu, ms, off);
    if ((tid & 31) == 0) wsum[tid >> 5] = ms;
    __syncthreads();
    if (tid < 8) {
        float t = wsum[tid];
#pragma unroll
        for (int off = 4; off > 0; off >>= 1)
            t += __shfl_xor_sync(0xffu, t, off);
        if (tid == 0) atomicAdd(&g_hist_sum, t);
    }
}

// ---------------------------------------------------------------------------
// Kernel C: combine the two scalars into el; zero them for the next replay.
// ---------------------------------------------------------------------------
__global__ void lfq_final(float* __restrict__ out) {
    if (threadIdx.x == 0) {
        // el = entro_mean - mean_entro = ent_sum/N + sum a*log(a+eps)
        out[Q_ELEMS] = g_ent_sum * (1.0f / (float)NSAMP) + g_hist_sum;
        g_ent_sum  = 0.0f;
        g_hist_sum = 0.0f;
    }
}

extern "C" void kernel_launch(void* const* d_in, const int* in_sizes, int n_in,
                              void* d_out, int out_size) {
    const float* x = (const float*)d_in[0];
    float* out = (float*)d_out;

    lfq_main<<<NSAMP / TPB, TPB>>>(x, out);
    lfq_hist<<<K_CODES / 256, 256>>>();
    lfq_final<<<1, 32>>>(out);
}

// round 4
// speedup vs baseline: 22.4825x; 1.9600x over previous
#include <cuda_runtime.h>

#define K_CODES 16384
#define NSAMP   4096
#define DIM     14
#define HW      1024
#define Q_ELEMS 57344            // 4 * 14 * 1024
#define WPB     8                // warps per block (kernel A)

// Module-load zero-initialized; every call restores zeros behind itself so
// each execution (eager correctness run or graph replay) starts identically.
__device__ float g_avg[K_CODES];
__device__ float g_ent_sum;
__device__ float g_hist_sum;
__device__ int   g_done;

__device__ __forceinline__ float warp_sum(float v) {
#pragma unroll
    for (int off = 16; off > 0; off >>= 1)
        v += __shfl_xor_sync(0xffffffffu, v, off);
    return v;
}

// ---------------------------------------------------------------------------
// Kernel A: ONE WARP PER SAMPLE (4096 warps; 512 blocks x 256).
//   lane j<14 owns dim j. Ballot -> index; shuffle reductions -> norm,
//   closed-form logS and entropy (softmax over +-1 codes factorizes into a
//   product of per-dim Bernoullis -> exact O(DIM) forms).
//   Survivor scatter: lane = subset mask of the "small" dims (flip cost
//   a_j = 400|xn_j| < 30); dropped probs < e^-30, below fp32 noise.
// ---------------------------------------------------------------------------
__global__ __launch_bounds__(32 * WPB) void lfq_main(const float* __restrict__ x,
                                                     float* __restrict__ out) {
    __shared__ float sc[WPB][DIM];
    __shared__ int   st[WPB][DIM];
    __shared__ float wents[WPB];

    const int wid  = threadIdx.x >> 5;
    const int lane = threadIdx.x & 31;
    const int s    = blockIdx.x * WPB + wid;    // sample id
    const int b    = s >> 10;
    const int n    = s & (HW - 1);

    float v = 0.0f;
    if (lane < DIM) {
        v = x[(b * DIM + lane) * HW + n];
        out[(b * DIM + lane) * HW + n] = (v > 0.0f) ? 1.0f : -1.0f;
    }

    const float inv = rsqrtf(warp_sum(v * v));

    const unsigned bal = __ballot_sync(0xffffffffu, v > 0.0f) & 0x3FFFu;
    const int idx = (int)(__brev(bal) >> 18);    // big-endian bit order
    if (lane == 0) out[Q_ELEMS + 1 + s] = (float)idx;

    const float a = (lane < DIM) ? 400.0f * fabsf(v) * inv : 1e30f;
    const float e = __expf(-a);                  // 0 for lanes >= DIM
    const float logS = warp_sum(log1pf(e));
    const float ent  = logS + warp_sum(a * e / (1.0f + e));  // exact entropy
    if (lane == 0) wents[wid] = ent;

    // gather small dims into shared, ranked
    const bool small = (lane < DIM) && (a < 30.0f);
    const unsigned bm = __ballot_sync(0xffffffffu, small);
    const int m = __popc(bm);
    if (small) {
        const int rank = __popc(bm & ((1u << lane) - 1u));
        sc[wid][rank] = a;
        st[wid][rank] = 1 << (13 - lane);
    }
    __syncwarp();

    // survivor scatter: lane = mask (one iteration for ~95% of samples)
    const float invS = __expf(-logS);
    const int nm = 1 << m;
    for (int mask = lane; mask < nm; mask += 32) {
        float c = 0.0f;
        int tog = 0;
        for (int j = 0; j < m; j++)
            if ((mask >> j) & 1) { c += sc[wid][j]; tog ^= st[wid][j]; }
        if (c < 30.0f)
            atomicAdd(&g_avg[idx ^ tog], __expf(-c) * invS);
    }

    // block-level entropy reduction -> one atomic per block
    __syncthreads();
    if (threadIdx.x < WPB) {
        float t = wents[threadIdx.x];
#pragma unroll
        for (int off = WPB / 2; off > 0; off >>= 1)
            t += __shfl_xor_sync((1u << WPB) - 1u, t, off);
        if (threadIdx.x == 0) atomicAdd(&g_ent_sum, t);
    }
}

// ---------------------------------------------------------------------------
// Kernel B: 64 blocks x 256, one histogram entry per thread.
// Accumulates sum_k avg*log(avg+eps), zeroes the histogram behind itself,
// and the LAST block combines both scalars into el and resets state.
// ---------------------------------------------------------------------------
__global__ __launch_bounds__(256) void lfq_hist(float* __restrict__ out) {
    __shared__ float wsum[8];
    const int tid = threadIdx.x;
    const int i   = blockIdx.x * 256 + tid;

    const float a = g_avg[i] * (1.0f / (float)NSAMP);
    g_avg[i] = 0.0f;
    float ms = a * logf(a + 1e-9f);

    ms = warp_sum(ms);
    if ((tid & 31) == 0) wsum[tid >> 5] = ms;
    __syncthreads();
    if (tid < 8) {
        float t = wsum[tid];
#pragma unroll
        for (int off = 4; off > 0; off >>= 1)
            t += __shfl_xor_sync(0xffu, t, off);
        if (tid == 0) {
            atomicAdd(&g_hist_sum, t);
            __threadfence();
            const int v = atomicAdd(&g_done, 1);
            if (v == (K_CODES / 256) - 1) {
                // el = entro_mean - mean_entro = ent_sum/N + sum a*log(a+eps)
                const float hs = atomicAdd(&g_hist_sum, 0.0f);
                const float es = atomicAdd(&g_ent_sum, 0.0f);
                out[Q_ELEMS] = es * (1.0f / (float)NSAMP) + hs;
                g_hist_sum = 0.0f;
                g_ent_sum  = 0.0f;
                g_done     = 0;
            }
        }
    }
}

extern "C" void kernel_launch(void* const* d_in, const int* in_sizes, int n_in,
                              void* d_out, int out_size) {
    const float* x = (const float*)d_in[0];
    float* out = (float*)d_out;

    lfq_main<<<NSAMP / WPB, 32 * WPB>>>(x, out);
    lfq_hist<<<K_CODES / 256, 256>>>(out);
}